// round 4
// baseline (speedup 1.0000x reference)
#include <cuda_runtime.h>
#include <cuda_bf16.h>

// Problem constants (from reference)
#define Bn    32768
#define Gn    25
#define INn   128
#define NCn   3
#define OUTn  75
#define ROWW  (Gn * INn)          // 3200 floats per x row
#define BQ    (Bn / 4)            // 8192 b-quads per g
#define QUADS (Gn * BQ)           // 204800 quads (same-g, 4 consecutive b)
#define PAIRS (QUADS / 2)         // 102400 (pairs never cross a g boundary; BQ even)

#define K_STRIDE 136              // ints per K row (pad)
#define W_STRIDE 392              // floats per weight group (3*128 + 8 pad), 16B mult

#define NBLOCK 2048
#define NTHREAD 256

__global__ __launch_bounds__(NTHREAD)
void mlp_rsna9_kernel(const float* __restrict__ x,
                      const int*   __restrict__ Kp,
                      const int*   __restrict__ Vp,
                      const float* __restrict__ Wsp, const float* __restrict__ bsp,
                      const float* __restrict__ Wnf, const float* __restrict__ bnf,
                      const float* __restrict__ Wss, const float* __restrict__ bss,
                      float* __restrict__ out)
{
    __shared__ int   K_s[Gn * K_STRIDE];
    __shared__ __align__(16) float W_s[3 * W_STRIDE]; // grp*392 + c*128 + i
    __shared__ int   V_s[OUTn + 1];
    __shared__ float bias_s[12];
    __shared__ int   Kbase_s[Gn];
    __shared__ int   Kflag_s[Gn];

    const int tid = threadIdx.x;

    // ---- stage K ----
    for (int idx = tid; idx < Gn * INn; idx += NTHREAD) {
        int g = idx >> 7, i = idx & 127;
        K_s[g * K_STRIDE + i] = Kp[idx];
    }
    // ---- stage W transposed: W_s[grp][c][i] = Wgrp[i*3 + c] ----
    for (int idx = tid; idx < 3 * NCn * INn; idx += NTHREAD) {
        int grp = idx / (NCn * INn);
        int rem = idx - grp * (NCn * INn);
        int c = rem >> 7, i = rem & 127;
        const float* Wg = (grp == 0) ? Wsp : (grp == 1) ? Wnf : Wss;
        W_s[grp * W_STRIDE + c * INn + i] = Wg[i * NCn + c];
    }
    if (tid < OUTn) V_s[tid] = Vp[tid];
    if (tid < 9) {
        int grp = tid / 3, c = tid - grp * 3;
        const float* bg = (grp == 0) ? bsp : (grp == 1) ? bnf : bss;
        bias_s[tid] = bg[c];
    }
    __syncthreads();

    // ---- per-row contiguity check (enables float4 fast path) ----
    if (tid < Gn) {
        const int* Krow = K_s + tid * K_STRIDE;
        int base = Krow[0];
        int ok = ((base & 3) == 0) ? 1 : 0;
        #pragma unroll 8
        for (int i = 1; i < INn; i++) ok &= (Krow[i] == base + i) ? 1 : 0;
        Kbase_s[tid] = base;
        Kflag_s[tid] = ok;
    }
    __syncthreads();

    const int lane = tid & 31;
    const int warp = tid >> 5;
    const int sub  = lane & 7;     // position within 8-lane task group
    const int q    = lane >> 3;    // which of 4 b's in a quad

    const int warp_global = blockIdx.x * (NTHREAD / 32) + warp;
    const int total_warps = gridDim.x * (NTHREAD / 32);

    for (int pp = warp_global; pp < PAIRS; pp += total_warps) {
        const int qq  = pp * 2;                // first quad of the pair
        const int g   = qq >> 13;              // / 8192  (same g for both quads)
        const int bq  = qq & (BQ - 1);
        const int bA  = (bq    ) * 4 + q;      // quad A batch index
        const int bB  = (bq + 1) * 4 + q;      // quad B batch index
        const int grp = (g < 5) ? 0 : (g < 15) ? 1 : 2;

        float a0 = 0.f, a1 = 0.f, a2 = 0.f;    // quad A accumulators
        float c0 = 0.f, c1 = 0.f, c2 = 0.f;    // quad B accumulators

        if (Kflag_s[g]) {
            const int   base = Kbase_s[g];
            const float4* xA = reinterpret_cast<const float4*>(x + (size_t)bA * ROWW + base);
            const float4* xB = reinterpret_cast<const float4*>(x + (size_t)bB * ROWW + base);
            const float4* w4 = reinterpret_cast<const float4*>(W_s + grp * W_STRIDE);
            #pragma unroll
            for (int t = 0; t < 4; t++) {
                const int f = sub + 8 * t;            // float4 index 0..31 (same across q -> W broadcast)
                const float4 va = __ldg(xA + f);
                const float4 vb = __ldg(xB + f);
                const float4 w0 = w4[f];              // c = 0 (broadcast LDS)
                const float4 w1 = w4[32 + f];         // c = 1
                const float4 w2 = w4[64 + f];         // c = 2
                a0 = fmaf(va.x, w0.x, a0); a0 = fmaf(va.y, w0.y, a0);
                a0 = fmaf(va.z, w0.z, a0); a0 = fmaf(va.w, w0.w, a0);
                a1 = fmaf(va.x, w1.x, a1); a1 = fmaf(va.y, w1.y, a1);
                a1 = fmaf(va.z, w1.z, a1); a1 = fmaf(va.w, w1.w, a1);
                a2 = fmaf(va.x, w2.x, a2); a2 = fmaf(va.y, w2.y, a2);
                a2 = fmaf(va.z, w2.z, a2); a2 = fmaf(va.w, w2.w, a2);
                c0 = fmaf(vb.x, w0.x, c0); c0 = fmaf(vb.y, w0.y, c0);
                c0 = fmaf(vb.z, w0.z, c0); c0 = fmaf(vb.w, w0.w, c0);
                c1 = fmaf(vb.x, w1.x, c1); c1 = fmaf(vb.y, w1.y, c1);
                c1 = fmaf(vb.z, w1.z, c1); c1 = fmaf(vb.w, w1.w, c1);
                c2 = fmaf(vb.x, w2.x, c2); c2 = fmaf(vb.y, w2.y, c2);
                c2 = fmaf(vb.z, w2.z, c2); c2 = fmaf(vb.w, w2.w, c2);
            }
        } else {
            // ---- fallback: honest gather via K ----
            const float* xAr = x + (size_t)bA * ROWW;
            const float* xBr = x + (size_t)bB * ROWW;
            const int*   Krow = K_s + g * K_STRIDE;
            const float* w0   = W_s + grp * W_STRIDE;
            #pragma unroll
            for (int t = 0; t < 16; t++) {
                const int i  = sub + 8 * t;
                const int kv = Krow[i];
                const float va = __ldg(xAr + kv);
                const float vb = __ldg(xBr + kv);
                const float wa = w0[i], wb = w0[INn + i], wc = w0[2*INn + i];
                a0 = fmaf(va, wa, a0); a1 = fmaf(va, wb, a1); a2 = fmaf(va, wc, a2);
                c0 = fmaf(vb, wa, c0); c1 = fmaf(vb, wb, c1); c2 = fmaf(vb, wc, c2);
            }
        }

        // butterfly reduction within each 8-lane group
        #pragma unroll
        for (int m = 4; m >= 1; m >>= 1) {
            a0 += __shfl_xor_sync(0xffffffffu, a0, m);
            a1 += __shfl_xor_sync(0xffffffffu, a1, m);
            a2 += __shfl_xor_sync(0xffffffffu, a2, m);
            c0 += __shfl_xor_sync(0xffffffffu, c0, m);
            c1 += __shfl_xor_sync(0xffffffffu, c1, m);
            c2 += __shfl_xor_sync(0xffffffffu, c2, m);
        }

        if (sub < NCn) {
            const int vcol = V_s[g * NCn + sub];
            const float bia = bias_s[grp * 3 + sub];
            float sa = (sub == 0) ? a0 : (sub == 1) ? a1 : a2;
            float sb = (sub == 0) ? c0 : (sub == 1) ? c1 : c2;
            out[(size_t)bA * OUTn + vcol] = sa + bia;
            out[(size_t)bB * OUTn + vcol] = sb + bia;
        }
    }
}

extern "C" void kernel_launch(void* const* d_in, const int* in_sizes, int n_in,
                              void* d_out, int out_size)
{
    const float* x   = (const float*)d_in[0];
    const int*   K   = (const int*)  d_in[1];
    const int*   V   = (const int*)  d_in[2];
    const float* Wsp = (const float*)d_in[3];
    const float* bsp = (const float*)d_in[4];
    const float* Wnf = (const float*)d_in[5];
    const float* bnf = (const float*)d_in[6];
    const float* Wss = (const float*)d_in[7];
    const float* bss = (const float*)d_in[8];
    float* out = (float*)d_out;

    mlp_rsna9_kernel<<<NBLOCK, NTHREAD>>>(x, K, V, Wsp, bsp, Wnf, bnf, Wss, bss, out);
}